// round 1
// baseline (speedup 1.0000x reference)
#include <cuda_runtime.h>

#define N_PTS 160000
#define C 64
#define SCALE_XY 2073600
#define PID_SPACE (2*SCALE_XY)              /* 4,147,200 */
#define SCAN_BLK 256
#define SCAN_ITEMS 16
#define SCAN_TILE (SCAN_BLK*SCAN_ITEMS)     /* 4096 */
#define NB1 ((PID_SPACE + SCAN_TILE - 1)/SCAN_TILE)  /* 1013 */
#define PID_PAD (NB1*SCAN_TILE)             /* 4,149,248 */

// ---------------- scratch (static device globals; no allocation) -------------
__device__ unsigned int       g_zmask[PID_PAD];    // per-pillar z-bin occupancy bits
__device__ int                g_prank[PID_PAD];    // exclusive scan of (zmask!=0) -> pillar sorted rank
__device__ int                g_vbase[PID_PAD];    // exclusive scan of popc(zmask) -> compact voxel base
__device__ float              g_h[(size_t)N_PTS*C];       // pts[:,1:9] @ W
__device__ float              g_voxsum[(size_t)N_PTS*C];  // compact per-voxel feature sums
__device__ int                g_voxcnt[N_PTS];
__device__ int                g_zi[N_PTS];
__device__ int                g_pidlist[N_PTS];    // pillar rank -> pid
__device__ unsigned long long g_bsums[NB1];        // packed (o<<32)|v block sums
__device__ float              g_bnsum[C], g_bnsq[C];
__device__ float              g_scale[C], g_shift[C];
__device__ int                g_P;                 // number of real pillars
__device__ int                g_V;                 // number of real voxels

// ---------------- zero scratch ----------------
__global__ void kzero() {
    int i = blockIdx.x * blockDim.x + threadIdx.x;
    int stride = gridDim.x * blockDim.x;
    for (int j = i; j < PID_PAD; j += stride) g_zmask[j] = 0u;
    for (int j = i; j < N_PTS * C; j += stride) g_voxsum[j] = 0.0f;
    for (int j = i; j < N_PTS; j += stride) g_voxcnt[j] = 0;
    if (i < C) { g_bnsum[i] = 0.0f; g_bnsq[i] = 0.0f; }
}

// ---------------- h = pts[:,1:9] @ W, BN partial sums, z-mask build ----------
__global__ void k_mm_bn(const float* __restrict__ pts,
                        const float* __restrict__ W,
                        const int*   __restrict__ pmc) {
    __shared__ float sW[8 * 64];
    for (int t = threadIdx.x; t < 512; t += blockDim.x) sW[t] = W[t];
    __syncthreads();

    int c = threadIdx.x & 63;
    int sub = threadIdx.x >> 6;           // 4 points per 256-thread block
    float lsum = 0.0f, lsq = 0.0f;

    for (int i = blockIdx.x * 4 + sub; i < N_PTS; i += gridDim.x * 4) {
        const float* p = pts + (size_t)i * 9;
        float h = 0.0f;
        #pragma unroll
        for (int k = 0; k < 8; k++) h = fmaf(p[1 + k], sW[k * 64 + c], h);
        g_h[(size_t)i * C + c] = h;
        lsum += h; lsq += h * h;
        if (c == 0) {
            int zi = (int)floorf(p[6]);   // z in [0,16), voxel z size 1.0
            g_zi[i] = zi;
            atomicOr(&g_zmask[pmc[i]], 1u << zi);
        }
    }

    __shared__ float ss[256], sq2[256];
    ss[threadIdx.x] = lsum; sq2[threadIdx.x] = lsq;
    __syncthreads();
    if (sub == 0) {
        atomicAdd(&g_bnsum[c], ss[c] + ss[64 + c] + ss[128 + c] + ss[192 + c]);
        atomicAdd(&g_bnsq[c],  sq2[c] + sq2[64 + c] + sq2[128 + c] + sq2[192 + c]);
    }
}

// ---------------- BN finalize: scale/shift ----------------
__global__ void k_bnfin(const float* __restrict__ gamma, const float* __restrict__ beta) {
    int c = threadIdx.x;
    float mu  = g_bnsum[c] / (float)N_PTS;
    float var = g_bnsq[c] / (float)N_PTS - mu * mu;   // biased var, matches jnp.var
    float s = gamma[c] * rsqrtf(var + 1e-3f);
    g_scale[c] = s;
    g_shift[c] = beta[c] - mu * s;
}

// ---------------- dual exclusive scan over pid space (3 kernels) -------------
__device__ __forceinline__ unsigned long long pack_ov(unsigned m) {
    return ((unsigned long long)(m != 0u) << 32) | (unsigned)__popc(m);
}

__global__ void k_scan1() {
    int base = blockIdx.x * SCAN_TILE + threadIdx.x * SCAN_ITEMS;
    unsigned long long acc = 0ULL;
    #pragma unroll
    for (int k = 0; k < SCAN_ITEMS; k++) acc += pack_ov(g_zmask[base + k]);
    __shared__ unsigned long long s[SCAN_BLK];
    s[threadIdx.x] = acc;
    __syncthreads();
    for (int off = SCAN_BLK / 2; off > 0; off >>= 1) {
        if (threadIdx.x < off) s[threadIdx.x] += s[threadIdx.x + off];
        __syncthreads();
    }
    if (threadIdx.x == 0) g_bsums[blockIdx.x] = s[0];
}

__global__ void k_scan2() {
    __shared__ unsigned long long s[1024];
    int t = threadIdx.x;
    unsigned long long x = (t < NB1) ? g_bsums[t] : 0ULL;
    s[t] = x;
    __syncthreads();
    for (int off = 1; off < 1024; off <<= 1) {
        unsigned long long v = (t >= off) ? s[t - off] : 0ULL;
        __syncthreads();
        s[t] += v;
        __syncthreads();
    }
    if (t < NB1) g_bsums[t] = s[t] - x;       // exclusive
    if (t == 1023) {
        unsigned long long tot = s[1023];
        g_P = (int)(tot >> 32);
        g_V = (int)(tot & 0xFFFFFFFFULL);
    }
}

__global__ void k_scan3() {
    int t = threadIdx.x;
    int base = blockIdx.x * SCAN_TILE + t * SCAN_ITEMS;
    unsigned long long run = 0ULL;
    unsigned long long pre[SCAN_ITEMS];
    #pragma unroll
    for (int k = 0; k < SCAN_ITEMS; k++) {
        pre[k] = run;
        run += pack_ov(g_zmask[base + k]);
    }
    __shared__ unsigned long long s[SCAN_BLK];
    s[t] = run;
    __syncthreads();
    for (int off = 1; off < SCAN_BLK; off <<= 1) {
        unsigned long long v = (t >= off) ? s[t - off] : 0ULL;
        __syncthreads();
        s[t] += v;
        __syncthreads();
    }
    unsigned long long off0 = g_bsums[blockIdx.x] + (s[t] - run);
    #pragma unroll
    for (int k = 0; k < SCAN_ITEMS; k++) {
        int idx = base + k;
        unsigned long long e = off0 + pre[k];
        int pr = (int)(e >> 32);
        g_prank[idx] = pr;
        g_vbase[idx] = (int)(e & 0xFFFFFFFFULL);
        if (g_zmask[idx]) g_pidlist[pr] = idx;
    }
}

// ---------------- per-point feature + voxel scatter-add ----------------------
__global__ void k_scatter(const float* __restrict__ sparse,
                          const int*   __restrict__ pmc) {
    int c = threadIdx.x & 63;
    int sub = threadIdx.x >> 6;
    int i = blockIdx.x * 4 + sub;
    if (i >= N_PTS) return;
    int pid = pmc[i];
    int r   = g_prank[pid];
    unsigned m = g_zmask[pid];
    int zi  = g_zi[i];
    int slot = g_vbase[pid] + __popc(m & ((1u << zi) - 1u));
    float pf = sparse[(size_t)r * C + c]
             + fmaxf(fmaf(g_h[(size_t)i * C + c], g_scale[c], g_shift[c]), 0.0f);
    atomicAdd(&g_voxsum[(size_t)slot * C + c], pf);
    if (c == 0) atomicAdd(&g_voxcnt[slot], 1);
}

// ---------------- fused output: sparse + masked per-pillar z-max -------------
__global__ void k_out(float* __restrict__ out, const float* __restrict__ sparse) {
    int c = threadIdx.x & 63;
    int sub = threadIdx.x >> 6;
    int r = blockIdx.x * 4 + sub;
    if (r >= N_PTS) return;
    float v = sparse[(size_t)r * C + c];
    if (r < g_P) {
        int pid = g_pidlist[r];
        unsigned m = g_zmask[pid];
        int nv = __popc(m);
        if (nv >= 2) {                       // occupied: pcnt >= 2
            int base = g_vbase[pid];
            float mx = -3.4e38f;
            for (int j = 0; j < nv; j++) {
                float cnt = (float)g_voxcnt[base + j];
                mx = fmaxf(mx, g_voxsum[(size_t)(base + j) * C + c] / cnt);
            }
            if (nv < 16) mx = fmaxf(mx, 0.0f);  // zero-filled unused z bins join the max
            v += mx;
        }
    }
    out[(size_t)r * C + c] = v;
}

// ---------------- launch ----------------
extern "C" void kernel_launch(void* const* d_in, const int* in_sizes, int n_in,
                              void* d_out, int out_size) {
    const float* pts    = (const float*)d_in[0];  // [N,9]
    const float* sparse = (const float*)d_in[1];  // [N,64]
    const float* W      = (const float*)d_in[2];  // [8,64]
    const float* gamma  = (const float*)d_in[3];  // [64]
    const float* beta   = (const float*)d_in[4];  // [64]
    const int*   pmc    = (const int*)d_in[5];    // [N]
    float* out = (float*)d_out;

    kzero<<<2048, 256>>>();
    k_mm_bn<<<1184, 256>>>(pts, W, pmc);
    k_bnfin<<<1, 64>>>(gamma, beta);
    k_scan1<<<NB1, SCAN_BLK>>>();
    k_scan2<<<1, 1024>>>();
    k_scan3<<<NB1, SCAN_BLK>>>();
    k_scatter<<<(N_PTS + 3) / 4, 256>>>(sparse, pmc);
    k_out<<<(N_PTS + 3) / 4, 256>>>(out, sparse);
}

// round 2
// speedup vs baseline: 2.0053x; 2.0053x over previous
#include <cuda_runtime.h>

#define N_PTS 160000
#define C 64
#define SCALE_XY 2073600
#define PID_SPACE (2*SCALE_XY)              /* 4,147,200 pids */
#define WORDS (PID_SPACE/2)                 /* 2,073,600 u32 words, 2 pids/word */
#define SCAN_BLK 256
#define WPT 8                               /* words per thread */
#define TILE_W (SCAN_BLK*WPT)               /* 2048 words = 4096 pids */
#define NB1 ((WORDS + TILE_W - 1)/TILE_W)   /* 1013 */
#define WORDS_PAD (NB1*TILE_W)              /* 2,074,624 */

// ---------------- static scratch ----------------
__device__ unsigned int       g_zmask32[WORDS_PAD];     // 2 pillars per word (16 z-bits each)
__device__ unsigned int       g_vbase[PID_SPACE];       // written ONLY at occupied pids
__device__ float              g_voxsum[(size_t)N_PTS*C];
__device__ int                g_voxcnt[N_PTS];
__device__ int                g_pidlist[N_PTS];         // pillar rank -> pid
__device__ unsigned long long g_bsums[NB1];             // packed (occ<<32)|voxcnt tile sums
__device__ double             g_s[8];                   // sum x_k
__device__ double             g_m[36];                  // sum x_k x_l, lower triangle
__device__ float              g_W2[512];                // W * scale (BN folded)
__device__ float              g_shift[C];
__device__ int                g_P;                      // # real pillars

__device__ __forceinline__ unsigned long long pack_ov(unsigned w) {
    unsigned occ = (unsigned)((w & 0xffffu) != 0u) + (unsigned)((w >> 16) != 0u);
    return ((unsigned long long)occ << 32) | (unsigned)__popc(w);
}

// ---------------- zero scratch ----------------
__global__ void kzero() {
    size_t i = (size_t)blockIdx.x * blockDim.x + threadIdx.x;
    size_t stride = (size_t)gridDim.x * blockDim.x;
    uint4 z4 = make_uint4(0u, 0u, 0u, 0u);
    uint4* zm = (uint4*)g_zmask32;
    for (size_t j = i; j < WORDS_PAD / 4; j += stride) zm[j] = z4;
    float4 f4 = make_float4(0.f, 0.f, 0.f, 0.f);
    float4* vs = (float4*)g_voxsum;
    for (size_t j = i; j < (size_t)N_PTS * C / 4; j += stride) vs[j] = f4;
    for (size_t j = i; j < N_PTS; j += stride) g_voxcnt[j] = 0;
    if (i < 8)  g_s[i] = 0.0;
    if (i < 36) g_m[i] = 0.0;
}

// -------- moment reduction over points + z-mask build (no h materialized) ----
__global__ void k_stats(const float* __restrict__ pts, const int* __restrict__ pmc) {
    float s[8]; float m[36];
    #pragma unroll
    for (int k = 0; k < 8; k++) s[k] = 0.f;
    #pragma unroll
    for (int k = 0; k < 36; k++) m[k] = 0.f;

    int tid = blockIdx.x * blockDim.x + threadIdx.x;
    int stride = gridDim.x * blockDim.x;
    for (int i = tid; i < N_PTS; i += stride) {
        const float* p = pts + (size_t)i * 9;
        float x[8];
        #pragma unroll
        for (int k = 0; k < 8; k++) x[k] = p[1 + k];
        #pragma unroll
        for (int k = 0; k < 8; k++) {
            s[k] += x[k];
            #pragma unroll
            for (int l = 0; l <= k; l++) m[k * (k + 1) / 2 + l] += x[k] * x[l];
        }
        int zi = (int)x[5];                 // z in [0,16), voxel z size = 1
        int pid = pmc[i];
        atomicOr(&g_zmask32[pid >> 1], (1u << zi) << ((pid & 1) * 16));
    }
    // warp reduce
    #pragma unroll
    for (int o = 16; o > 0; o >>= 1) {
        #pragma unroll
        for (int k = 0; k < 8; k++)  s[k] += __shfl_down_sync(0xffffffffu, s[k], o);
        #pragma unroll
        for (int k = 0; k < 36; k++) m[k] += __shfl_down_sync(0xffffffffu, m[k], o);
    }
    __shared__ double sd[44];
    if (threadIdx.x < 44) sd[threadIdx.x] = 0.0;
    __syncthreads();
    if ((threadIdx.x & 31) == 0) {
        for (int k = 0; k < 8;  k++) atomicAdd(&sd[k],     (double)s[k]);
        for (int k = 0; k < 36; k++) atomicAdd(&sd[8 + k], (double)m[k]);
    }
    __syncthreads();
    if (threadIdx.x < 8)                        atomicAdd(&g_s[threadIdx.x],      sd[threadIdx.x]);
    if (threadIdx.x >= 8 && threadIdx.x < 44)   atomicAdd(&g_m[threadIdx.x - 8],  sd[threadIdx.x]);
}

// ---------------- BN finalize: fold scale into W ----------------
__global__ void k_bnfin(const float* __restrict__ W,
                        const float* __restrict__ gamma,
                        const float* __restrict__ beta) {
    int c = threadIdx.x;
    double wc[8];
    #pragma unroll
    for (int k = 0; k < 8; k++) wc[k] = (double)W[k * 64 + c];
    const double invn = 1.0 / (double)N_PTS;
    double mu = 0.0;
    #pragma unroll
    for (int k = 0; k < 8; k++) mu += g_s[k] * invn * wc[k];
    double e2 = 0.0;
    #pragma unroll
    for (int k = 0; k < 8; k++) {
        for (int l = 0; l < k; l++) e2 += 2.0 * g_m[k * (k + 1) / 2 + l] * invn * wc[k] * wc[l];
        e2 += g_m[k * (k + 1) / 2 + k] * invn * wc[k] * wc[k];
    }
    double var = e2 - mu * mu;
    double scale = (double)gamma[c] / sqrt(var + 1e-3);
    #pragma unroll
    for (int k = 0; k < 8; k++) g_W2[k * 64 + c] = (float)(wc[k] * scale);
    g_shift[c] = (float)((double)beta[c] - mu * scale);
}

// ---------------- tile sums (coalesced reduction) ----------------
__global__ void k_scan1() {
    size_t base = (size_t)blockIdx.x * TILE_W;
    unsigned long long acc = 0ULL;
    #pragma unroll
    for (int j = 0; j < WPT; j++)
        acc += pack_ov(g_zmask32[base + j * SCAN_BLK + threadIdx.x]);
    #pragma unroll
    for (int o = 16; o > 0; o >>= 1) acc += __shfl_down_sync(0xffffffffu, acc, o);
    __shared__ unsigned long long sw[8];
    if ((threadIdx.x & 31) == 0) sw[threadIdx.x >> 5] = acc;
    __syncthreads();
    if (threadIdx.x == 0) {
        unsigned long long t = 0ULL;
        #pragma unroll
        for (int k = 0; k < 8; k++) t += sw[k];
        g_bsums[blockIdx.x] = t;
    }
}

// ---------------- scan of tile sums ----------------
__global__ void k_scan2() {
    __shared__ unsigned long long s[1024];
    int t = threadIdx.x;
    unsigned long long x = (t < NB1) ? g_bsums[t] : 0ULL;
    s[t] = x;
    __syncthreads();
    for (int off = 1; off < 1024; off <<= 1) {
        unsigned long long v = (t >= off) ? s[t - off] : 0ULL;
        __syncthreads();
        s[t] += v;
        __syncthreads();
    }
    if (t < NB1) g_bsums[t] = s[t] - x;
    if (t == 1023) g_P = (int)(s[1023] >> 32);
}

// -------- downsweep: sparse writes of vbase + pidlist only at occupied pids ---
__global__ void k_scan3() {
    __shared__ unsigned int sw[TILE_W];
    __shared__ unsigned long long ss[SCAN_BLK];
    size_t base = (size_t)blockIdx.x * TILE_W;
    int t = threadIdx.x;
    #pragma unroll
    for (int j = 0; j < WPT; j++)
        sw[j * SCAN_BLK + t] = g_zmask32[base + j * SCAN_BLK + t];
    __syncthreads();
    unsigned long long run = 0ULL;
    #pragma unroll
    for (int j = 0; j < WPT; j++) run += pack_ov(sw[t * WPT + j]);
    ss[t] = run;
    __syncthreads();
    for (int off = 1; off < SCAN_BLK; off <<= 1) {
        unsigned long long v = (t >= off) ? ss[t - off] : 0ULL;
        __syncthreads();
        ss[t] += v;
        __syncthreads();
    }
    unsigned long long e = g_bsums[blockIdx.x] + (ss[t] - run);
    #pragma unroll
    for (int j = 0; j < WPT; j++) {
        unsigned w = sw[t * WPT + j];
        int pid0 = (int)((base + (size_t)t * WPT + j) * 2);
        unsigned lo = w & 0xffffu, hi = w >> 16;
        if (lo) {
            g_vbase[pid0] = (unsigned)(e & 0xffffffffu);
            g_pidlist[e >> 32] = pid0;
            e += (1ULL << 32) + (unsigned)__popc(lo);
        }
        if (hi) {
            g_vbase[pid0 + 1] = (unsigned)(e & 0xffffffffu);
            g_pidlist[e >> 32] = pid0 + 1;
            e += (1ULL << 32) + (unsigned)__popc(hi);
        }
    }
}

// ------ per-point: inline matmul+BN+ReLU, scatter-add into compact voxels -----
__global__ void k_scatter(const float* __restrict__ pts, const int* __restrict__ pmc) {
    __shared__ float sW2[512];
    __shared__ float sSh[64];
    __shared__ float sp[16][9];
    __shared__ int   sslot[16];
    int t = threadIdx.x;
    for (int j = t; j < 512; j += 256) sW2[j] = g_W2[j];
    if (t < 64) sSh[t] = g_shift[t];
    int i0 = blockIdx.x * 16;                 // N_PTS = 160000 = 10000 * 16
    if (t < 144) sp[t / 9][t % 9] = pts[(size_t)i0 * 9 + t];
    __syncthreads();
    int g = t >> 4, lane = t & 15;
    if (lane == 0) {
        int pid = pmc[i0 + g];
        unsigned w = g_zmask32[pid >> 1];
        unsigned zm = (w >> ((pid & 1) * 16)) & 0xffffu;
        int zi = (int)sp[g][6];
        int slot = (int)g_vbase[pid] + __popc(zm & ((1u << zi) - 1u));
        sslot[g] = slot;
        atomicAdd(&g_voxcnt[slot], 1);
    }
    __syncthreads();
    int slot = sslot[g];
    float x[8];
    #pragma unroll
    for (int k = 0; k < 8; k++) x[k] = sp[g][1 + k];
    float* dst = &g_voxsum[(size_t)slot * C + lane * 4];
    #pragma unroll
    for (int cc = 0; cc < 4; cc++) {
        int c = lane * 4 + cc;
        float h = sSh[c];
        #pragma unroll
        for (int k = 0; k < 8; k++) h = fmaf(x[k], sW2[k * 64 + c], h);
        atomicAdd(dst + cc, fmaxf(h, 0.0f));
    }
}

// ------ output: sparse + masked per-pillar z-max (sparse folded analytically) -
__global__ void k_out(float* __restrict__ out, const float* __restrict__ sparse) {
    int t = threadIdx.x;
    int g = t >> 4, lane = t & 15;
    int r = blockIdx.x * 16 + g;
    float4 sv = ((const float4*)sparse)[(size_t)r * 16 + lane];
    float4 res = sv;
    if (r < g_P) {
        int pid = g_pidlist[r];
        unsigned w = g_zmask32[pid >> 1];
        unsigned zm = (w >> ((pid & 1) * 16)) & 0xffffu;
        int nv = __popc(zm);
        if (nv >= 2) {                          // occupied: >=2 voxels in pillar
            int base = (int)g_vbase[pid];
            float4 mx = make_float4(-3.4e38f, -3.4e38f, -3.4e38f, -3.4e38f);
            for (int j = 0; j < nv; j++) {
                float cnt = (float)g_voxcnt[base + j];
                float4 v = ((const float4*)g_voxsum)[(size_t)(base + j) * 16 + lane];
                mx.x = fmaxf(mx.x, v.x / cnt);
                mx.y = fmaxf(mx.y, v.y / cnt);
                mx.z = fmaxf(mx.z, v.z / cnt);
                mx.w = fmaxf(mx.w, v.w / cnt);
            }
            // voxel_feat = sparse + mean(relu); src_max = max over filled bins,
            // zero rows join the max when nv < 16
            float4 cand = make_float4(sv.x + mx.x, sv.y + mx.y, sv.z + mx.z, sv.w + mx.w);
            if (nv < 16) {
                cand.x = fmaxf(cand.x, 0.f); cand.y = fmaxf(cand.y, 0.f);
                cand.z = fmaxf(cand.z, 0.f); cand.w = fmaxf(cand.w, 0.f);
            }
            res = make_float4(sv.x + cand.x, sv.y + cand.y, sv.z + cand.z, sv.w + cand.w);
        }
    }
    ((float4*)out)[(size_t)r * 16 + lane] = res;
}

// ---------------- launch ----------------
extern "C" void kernel_launch(void* const* d_in, const int* in_sizes, int n_in,
                              void* d_out, int out_size) {
    const float* pts    = (const float*)d_in[0];  // [N,9]
    const float* sparse = (const float*)d_in[1];  // [N,64]
    const float* W      = (const float*)d_in[2];  // [8,64]
    const float* gamma  = (const float*)d_in[3];  // [64]
    const float* beta   = (const float*)d_in[4];  // [64]
    const int*   pmc    = (const int*)d_in[5];    // [N]
    float* out = (float*)d_out;

    kzero   <<<2048, 256>>>();
    k_stats <<<296, 256>>>(pts, pmc);
    k_bnfin <<<1, 64>>>(W, gamma, beta);
    k_scan1 <<<NB1, SCAN_BLK>>>();
    k_scan2 <<<1, 1024>>>();
    k_scan3 <<<NB1, SCAN_BLK>>>();
    k_scatter<<<N_PTS / 16, 256>>>(pts, pmc);
    k_out   <<<N_PTS / 16, 256>>>(out, sparse);
}

// round 3
// speedup vs baseline: 2.7183x; 1.3556x over previous
#include <cuda_runtime.h>

#define N_PTS 160000
#define C 64
#define SCALE_XY 2073600
#define PID_SPACE (2*SCALE_XY)              /* 4,147,200 pids */
#define WORDS (PID_SPACE/2)                 /* 2,073,600 u32 words, 2 pids/word */
#define SCAN_BLK 256
#define WPT 8                               /* words per thread */
#define TILE_W (SCAN_BLK*WPT)               /* 2048 words = 4096 pids */
#define NB1 ((WORDS + TILE_W - 1)/TILE_W)   /* 1013 */
#define WORDS_PAD (NB1*TILE_W)

// ---------------- static scratch ----------------
__device__ unsigned int       g_zmask32[WORDS_PAD];  // 2 pillars/word, 16 z-bits each
__device__ unsigned int       g_vbase[PID_SPACE];    // written ONLY at occupied pids
__device__ int                g_pidlist[N_PTS];      // pillar rank -> pid
__device__ int                g_head[N_PTS];         // per-voxel point-list head (-1)
__device__ int                g_next[N_PTS];         // per-point list link
__device__ unsigned long long g_bsums[NB1];          // packed (occ<<32)|voxcnt tile sums
__device__ double             g_s[8];                // sum x_k
__device__ double             g_m[36];               // sum x_k x_l (lower tri)
__device__ float              g_W2[512];             // W * BN scale (folded)
__device__ float              g_shift[C];
__device__ int                g_P;                   // # real pillars

__device__ __forceinline__ unsigned long long pack_ov(unsigned w) {
    unsigned occ = (unsigned)((w & 0xffffu) != 0u) + (unsigned)((w >> 16) != 0u);
    return ((unsigned long long)occ << 32) | (unsigned)__popc(w);
}

// ---------------- zero scratch (9 MB) ----------------
__global__ void kzero() {
    size_t i = (size_t)blockIdx.x * blockDim.x + threadIdx.x;
    size_t stride = (size_t)gridDim.x * blockDim.x;
    uint4 z4 = make_uint4(0u, 0u, 0u, 0u);
    uint4* zm = (uint4*)g_zmask32;
    for (size_t j = i; j < WORDS_PAD / 4; j += stride) zm[j] = z4;
    int4 m1 = make_int4(-1, -1, -1, -1);
    int4* hd = (int4*)g_head;
    for (size_t j = i; j < N_PTS / 4; j += stride) hd[j] = m1;
    if (i < 8)  g_s[i] = 0.0;
    if (i < 36) g_m[i] = 0.0;
}

// -------- moment reduction over points + z-mask build --------
__global__ void k_stats(const float* __restrict__ pts, const int* __restrict__ pmc) {
    float s[8]; float m[36];
    #pragma unroll
    for (int k = 0; k < 8; k++) s[k] = 0.f;
    #pragma unroll
    for (int k = 0; k < 36; k++) m[k] = 0.f;

    int tid = blockIdx.x * blockDim.x + threadIdx.x;
    int stride = gridDim.x * blockDim.x;
    for (int i = tid; i < N_PTS; i += stride) {
        const float* p = pts + (size_t)i * 9;
        float x[8];
        #pragma unroll
        for (int k = 0; k < 8; k++) x[k] = p[1 + k];
        #pragma unroll
        for (int k = 0; k < 8; k++) {
            s[k] += x[k];
            #pragma unroll
            for (int l = 0; l <= k; l++) m[k * (k + 1) / 2 + l] += x[k] * x[l];
        }
        int zi = (int)x[5];                 // z in [0,16), voxel z size 1
        int pid = pmc[i];
        atomicOr(&g_zmask32[pid >> 1], (1u << zi) << ((pid & 1) * 16));
    }
    #pragma unroll
    for (int o = 16; o > 0; o >>= 1) {
        #pragma unroll
        for (int k = 0; k < 8; k++)  s[k] += __shfl_down_sync(0xffffffffu, s[k], o);
        #pragma unroll
        for (int k = 0; k < 36; k++) m[k] += __shfl_down_sync(0xffffffffu, m[k], o);
    }
    __shared__ double sd[44];
    if (threadIdx.x < 44) sd[threadIdx.x] = 0.0;
    __syncthreads();
    if ((threadIdx.x & 31) == 0) {
        for (int k = 0; k < 8;  k++) atomicAdd(&sd[k],     (double)s[k]);
        for (int k = 0; k < 36; k++) atomicAdd(&sd[8 + k], (double)m[k]);
    }
    __syncthreads();
    if (threadIdx.x < 8)                      atomicAdd(&g_s[threadIdx.x],     sd[threadIdx.x]);
    if (threadIdx.x >= 8 && threadIdx.x < 44) atomicAdd(&g_m[threadIdx.x - 8], sd[threadIdx.x]);
}

// ---------------- tile sums (vectorized, MLP=2 wide loads) ----------------
__global__ void k_scan1() {
    size_t base = (size_t)blockIdx.x * TILE_W + (size_t)threadIdx.x * WPT;
    uint4 a = *(const uint4*)&g_zmask32[base];
    uint4 b = *(const uint4*)&g_zmask32[base + 4];
    unsigned long long acc = pack_ov(a.x) + pack_ov(a.y) + pack_ov(a.z) + pack_ov(a.w)
                           + pack_ov(b.x) + pack_ov(b.y) + pack_ov(b.z) + pack_ov(b.w);
    #pragma unroll
    for (int o = 16; o > 0; o >>= 1) acc += __shfl_down_sync(0xffffffffu, acc, o);
    __shared__ unsigned long long sw[8];
    if ((threadIdx.x & 31) == 0) sw[threadIdx.x >> 5] = acc;
    __syncthreads();
    if (threadIdx.x == 0) {
        unsigned long long t = 0ULL;
        #pragma unroll
        for (int k = 0; k < 8; k++) t += sw[k];
        g_bsums[blockIdx.x] = t;
    }
}

// ---------------- scan of tile sums + BN finalize (merged) ----------------
__global__ void k_scan2(const float* __restrict__ W,
                        const float* __restrict__ gamma,
                        const float* __restrict__ beta) {
    int t = threadIdx.x;
    if (t < 64) {                          // BN fold (independent of scan)
        int c = t;
        double wc[8];
        #pragma unroll
        for (int k = 0; k < 8; k++) wc[k] = (double)W[k * 64 + c];
        const double invn = 1.0 / (double)N_PTS;
        double mu = 0.0;
        #pragma unroll
        for (int k = 0; k < 8; k++) mu += g_s[k] * invn * wc[k];
        double e2 = 0.0;
        #pragma unroll
        for (int k = 0; k < 8; k++) {
            for (int l = 0; l < k; l++) e2 += 2.0 * g_m[k * (k + 1) / 2 + l] * invn * wc[k] * wc[l];
            e2 += g_m[k * (k + 1) / 2 + k] * invn * wc[k] * wc[k];
        }
        double var = e2 - mu * mu;
        double scale = (double)gamma[c] / sqrt(var + 1e-3);
        #pragma unroll
        for (int k = 0; k < 8; k++) g_W2[k * 64 + c] = (float)(wc[k] * scale);
        g_shift[c] = (float)((double)beta[c] - mu * scale);
    }
    __shared__ unsigned long long s[1024];
    unsigned long long x = (t < NB1) ? g_bsums[t] : 0ULL;
    s[t] = x;
    __syncthreads();
    for (int off = 1; off < 1024; off <<= 1) {
        unsigned long long v = (t >= off) ? s[t - off] : 0ULL;
        __syncthreads();
        s[t] += v;
        __syncthreads();
    }
    if (t < NB1) g_bsums[t] = s[t] - x;
    if (t == 1023) g_P = (int)(s[1023] >> 32);
}

// -------- downsweep: sparse writes of vbase + pidlist at occupied pids --------
__global__ void k_scan3() {
    __shared__ unsigned int sw[TILE_W];
    __shared__ unsigned long long ss[SCAN_BLK];
    size_t base = (size_t)blockIdx.x * TILE_W;
    int t = threadIdx.x;
    #pragma unroll
    for (int j = 0; j < WPT; j++)
        sw[j * SCAN_BLK + t] = g_zmask32[base + j * SCAN_BLK + t];
    __syncthreads();
    unsigned long long run = 0ULL;
    #pragma unroll
    for (int j = 0; j < WPT; j++) run += pack_ov(sw[t * WPT + j]);
    ss[t] = run;
    __syncthreads();
    for (int off = 1; off < SCAN_BLK; off <<= 1) {
        unsigned long long v = (t >= off) ? ss[t - off] : 0ULL;
        __syncthreads();
        ss[t] += v;
        __syncthreads();
    }
    unsigned long long e = g_bsums[blockIdx.x] + (ss[t] - run);
    #pragma unroll
    for (int j = 0; j < WPT; j++) {
        unsigned w = sw[t * WPT + j];
        int pid0 = (int)((base + (size_t)t * WPT + j) * 2);
        unsigned lo = w & 0xffffu, hi = w >> 16;
        if (lo) {
            g_vbase[pid0] = (unsigned)(e & 0xffffffffu);
            g_pidlist[e >> 32] = pid0;
            e += (1ULL << 32) + (unsigned)__popc(lo);
        }
        if (hi) {
            g_vbase[pid0 + 1] = (unsigned)(e & 0xffffffffu);
            g_pidlist[e >> 32] = pid0 + 1;
            e += (1ULL << 32) + (unsigned)__popc(hi);
        }
    }
}

// -------- per-voxel point linked lists (one atomicExch per point) --------
__global__ void k_link(const float* __restrict__ pts, const int* __restrict__ pmc) {
    int i = blockIdx.x * blockDim.x + threadIdx.x;
    if (i >= N_PTS) return;
    int pid = pmc[i];
    int zi = (int)__ldg(&pts[(size_t)i * 9 + 6]);
    unsigned w = g_zmask32[pid >> 1];
    unsigned zm = (w >> ((pid & 1) * 16)) & 0xffffu;
    int slot = (int)g_vbase[pid] + __popc(zm & ((1u << zi) - 1u));
    g_next[i] = atomicExch(&g_head[slot], i);
}

// ------ output: traverse pillar's voxel chains, inline matmul+BN+ReLU --------
__global__ void k_out(float* __restrict__ out,
                      const float* __restrict__ sparse,
                      const float* __restrict__ pts) {
    __shared__ float sW2[512];
    __shared__ float sSh[64];
    int t = threadIdx.x;
    for (int j = t; j < 512; j += 256) sW2[j] = g_W2[j];
    if (t < 64) sSh[t] = g_shift[t];
    __syncthreads();
    int g = t >> 4, lane = t & 15;
    int r = blockIdx.x * 16 + g;
    float4 sv = ((const float4*)sparse)[(size_t)r * 16 + lane];
    float4 res = sv;
    if (r < g_P) {
        int pid = g_pidlist[r];
        unsigned w = g_zmask32[pid >> 1];
        unsigned zm = (w >> ((pid & 1) * 16)) & 0xffffu;
        int nv = __popc(zm);
        if (nv >= 2) {                      // occupied: >=2 voxels in pillar
            int base = (int)g_vbase[pid];
            int c0 = lane * 4;
            float4 mx = make_float4(-3.4e38f, -3.4e38f, -3.4e38f, -3.4e38f);
            for (int j = 0; j < nv; j++) {
                int idx = g_head[base + j];
                float a0 = 0.f, a1 = 0.f, a2 = 0.f, a3 = 0.f;
                int cnt = 0;
                while (idx >= 0) {
                    const float* p = pts + (size_t)idx * 9;
                    int nxt = g_next[idx];
                    float x[8];
                    #pragma unroll
                    for (int k = 0; k < 8; k++) x[k] = __ldg(&p[1 + k]);
                    float h0 = sSh[c0], h1 = sSh[c0 + 1], h2 = sSh[c0 + 2], h3 = sSh[c0 + 3];
                    #pragma unroll
                    for (int k = 0; k < 8; k++) {
                        h0 = fmaf(x[k], sW2[k * 64 + c0],     h0);
                        h1 = fmaf(x[k], sW2[k * 64 + c0 + 1], h1);
                        h2 = fmaf(x[k], sW2[k * 64 + c0 + 2], h2);
                        h3 = fmaf(x[k], sW2[k * 64 + c0 + 3], h3);
                    }
                    a0 += fmaxf(h0, 0.f); a1 += fmaxf(h1, 0.f);
                    a2 += fmaxf(h2, 0.f); a3 += fmaxf(h3, 0.f);
                    cnt++;
                    idx = nxt;
                }
                float ic = 1.0f / (float)cnt;
                mx.x = fmaxf(mx.x, a0 * ic);
                mx.y = fmaxf(mx.y, a1 * ic);
                mx.z = fmaxf(mx.z, a2 * ic);
                mx.w = fmaxf(mx.w, a3 * ic);
            }
            // voxel mean = sv + mean(relu); zero rows join the max when nv < 16
            float4 cand = make_float4(sv.x + mx.x, sv.y + mx.y, sv.z + mx.z, sv.w + mx.w);
            if (nv < 16) {
                cand.x = fmaxf(cand.x, 0.f); cand.y = fmaxf(cand.y, 0.f);
                cand.z = fmaxf(cand.z, 0.f); cand.w = fmaxf(cand.w, 0.f);
            }
            res = make_float4(sv.x + cand.x, sv.y + cand.y, sv.z + cand.z, sv.w + cand.w);
        }
    }
    ((float4*)out)[(size_t)r * 16 + lane] = res;
}

// ---------------- launch ----------------
extern "C" void kernel_launch(void* const* d_in, const int* in_sizes, int n_in,
                              void* d_out, int out_size) {
    const float* pts    = (const float*)d_in[0];  // [N,9]
    const float* sparse = (const float*)d_in[1];  // [N,64]
    const float* W      = (const float*)d_in[2];  // [8,64]
    const float* gamma  = (const float*)d_in[3];  // [64]
    const float* beta   = (const float*)d_in[4];  // [64]
    const int*   pmc    = (const int*)d_in[5];    // [N]
    float* out = (float*)d_out;

    kzero  <<<1024, 256>>>();
    k_stats<<<296, 256>>>(pts, pmc);
    k_scan1<<<NB1, SCAN_BLK>>>();
    k_scan2<<<1, 1024>>>(W, gamma, beta);
    k_scan3<<<NB1, SCAN_BLK>>>();
    k_link <<<(N_PTS + 255) / 256, 256>>>(pts, pmc);
    k_out  <<<N_PTS / 16, 256>>>(out, sparse, pts);
}

// round 4
// speedup vs baseline: 2.8757x; 1.0579x over previous
#include <cuda_runtime.h>

#define N_PTS 160000
#define C 64
#define SCALE_XY 2073600
#define PID_SPACE (2*SCALE_XY)              /* 4,147,200 pids */
#define WORDS (PID_SPACE/2)                 /* 2,073,600 u32 words, 2 pids/word */
#define SCAN_BLK 256
#define WPT 8                               /* words per thread */
#define TILE_W (SCAN_BLK*WPT)               /* 2048 words = 4096 pids */
#define NB1 ((WORDS + TILE_W - 1)/TILE_W)   /* 1013 */
#define WORDS_PAD (NB1*TILE_W)

#define FLAG_AGG (1ULL << 62)
#define FLAG_PRE (2ULL << 62)
#define VAL_MASK ((1ULL << 50) - 1)

// ---------------- static scratch ----------------
__device__ unsigned int       g_zmask32[WORDS_PAD];  // 2 pillars/word, 16 z-bits each
__device__ unsigned int       g_vbase[PID_SPACE];    // written ONLY at occupied pids
__device__ int                g_pidlist[N_PTS];      // pillar rank -> pid
__device__ int                g_head[N_PTS];         // per-voxel point-list head (-1)
__device__ int                g_next[N_PTS];         // per-point list link
__device__ unsigned long long g_state[NB1];          // decoupled-lookback tile state
__device__ double             g_s[8];                // sum x_k
__device__ double             g_m[36];               // sum x_k x_l (lower tri)
__device__ float              g_W2[512];             // W * BN scale (folded)
__device__ float              g_shift[C];
__device__ int                g_P;                   // # real pillars

__device__ __forceinline__ unsigned long long pack_ov(unsigned w) {
    unsigned occ = (unsigned)((w & 0xffffu) != 0u) + (unsigned)((w >> 16) != 0u);
    return ((unsigned long long)occ << 32) | (unsigned)__popc(w);
}
__device__ __forceinline__ unsigned long long vload(const unsigned long long* p) {
    return *(volatile const unsigned long long*)p;
}
__device__ __forceinline__ void vstore(unsigned long long* p, unsigned long long v) {
    *(volatile unsigned long long*)p = v;
}

// ---------------- zero scratch ----------------
__global__ void kzero() {
    size_t i = (size_t)blockIdx.x * blockDim.x + threadIdx.x;
    size_t stride = (size_t)gridDim.x * blockDim.x;
    uint4 z4 = make_uint4(0u, 0u, 0u, 0u);
    uint4* zm = (uint4*)g_zmask32;
    for (size_t j = i; j < WORDS_PAD / 4; j += stride) zm[j] = z4;
    int4 m1 = make_int4(-1, -1, -1, -1);
    int4* hd = (int4*)g_head;
    for (size_t j = i; j < N_PTS / 4; j += stride) hd[j] = m1;
    for (size_t j = i; j < NB1; j += stride) g_state[j] = 0ULL;
    if (i < 8)  g_s[i] = 0.0;
    if (i < 36) g_m[i] = 0.0;
}

// -------- moment reduction over points + z-mask build --------
__global__ void k_stats(const float* __restrict__ pts, const int* __restrict__ pmc) {
    float s[8]; float m[36];
    #pragma unroll
    for (int k = 0; k < 8; k++) s[k] = 0.f;
    #pragma unroll
    for (int k = 0; k < 36; k++) m[k] = 0.f;

    int tid = blockIdx.x * blockDim.x + threadIdx.x;
    int stride = gridDim.x * blockDim.x;
    for (int i = tid; i < N_PTS; i += stride) {
        const float* p = pts + (size_t)i * 9;
        float x[8];
        #pragma unroll
        for (int k = 0; k < 8; k++) x[k] = p[1 + k];
        #pragma unroll
        for (int k = 0; k < 8; k++) {
            s[k] += x[k];
            #pragma unroll
            for (int l = 0; l <= k; l++) m[k * (k + 1) / 2 + l] += x[k] * x[l];
        }
        int zi = (int)x[5];                 // z in [0,16), voxel z size 1
        int pid = pmc[i];
        atomicOr(&g_zmask32[pid >> 1], (1u << zi) << ((pid & 1) * 16));
    }
    #pragma unroll
    for (int o = 16; o > 0; o >>= 1) {
        #pragma unroll
        for (int k = 0; k < 8; k++)  s[k] += __shfl_down_sync(0xffffffffu, s[k], o);
        #pragma unroll
        for (int k = 0; k < 36; k++) m[k] += __shfl_down_sync(0xffffffffu, m[k], o);
    }
    __shared__ double sd[44];
    if (threadIdx.x < 44) sd[threadIdx.x] = 0.0;
    __syncthreads();
    if ((threadIdx.x & 31) == 0) {
        for (int k = 0; k < 8;  k++) atomicAdd(&sd[k],     (double)s[k]);
        for (int k = 0; k < 36; k++) atomicAdd(&sd[8 + k], (double)m[k]);
    }
    __syncthreads();
    if (threadIdx.x < 8)                      atomicAdd(&g_s[threadIdx.x],     sd[threadIdx.x]);
    if (threadIdx.x >= 8 && threadIdx.x < 44) atomicAdd(&g_m[threadIdx.x - 8], sd[threadIdx.x]);
}

// -------- single-pass scan: tile scan + decoupled lookback + downsweep --------
__global__ void k_scan() {
    __shared__ unsigned long long s_warp[8];
    __shared__ unsigned long long s_agg;
    __shared__ unsigned long long s_exc;
    int t = threadIdx.x;
    int lane = t & 31, wid = t >> 5;
    int bid = blockIdx.x;

    size_t base = (size_t)bid * TILE_W + (size_t)t * WPT;
    uint4 a = *(const uint4*)&g_zmask32[base];
    uint4 b = *(const uint4*)&g_zmask32[base + 4];
    unsigned w[8] = {a.x, a.y, a.z, a.w, b.x, b.y, b.z, b.w};
    unsigned long long pre[8], run = 0ULL;
    #pragma unroll
    for (int k = 0; k < 8; k++) { pre[k] = run; run += pack_ov(w[k]); }

    // warp inclusive scan
    unsigned long long inc = run;
    #pragma unroll
    for (int o = 1; o < 32; o <<= 1) {
        unsigned long long v = __shfl_up_sync(0xffffffffu, inc, o);
        if (lane >= o) inc += v;
    }
    if (lane == 31) s_warp[wid] = inc;
    __syncthreads();
    if (t < 8) {   // scan 8 warp totals
        unsigned long long x = s_warp[t];
        unsigned long long sc = x;
        #pragma unroll
        for (int o = 1; o < 8; o <<= 1) {
            unsigned long long v = __shfl_up_sync(0xffu, sc, o);
            if (t >= o) sc += v;
        }
        s_warp[t] = sc - x;                 // exclusive warp offset
        if (t == 7) s_agg = sc;             // block aggregate
    }
    __syncthreads();

    // warp 0: publish + lookback
    if (wid == 0) {
        unsigned long long agg = s_agg;
        if (bid == 0) {
            if (lane == 0) { vstore(&g_state[0], FLAG_PRE | agg); s_exc = 0ULL; }
        } else {
            if (lane == 0) vstore(&g_state[bid], FLAG_AGG | agg);
            unsigned long long exc = 0ULL;
            int end = bid;
            while (end > 0) {
                int start = end - 32; if (start < 0) start = 0;
                int j = start + lane;
                bool active = (j < end);
                unsigned long long st = 0ULL;
                do {
                    if (active) st = vload(&g_state[j]);
                } while (__any_sync(0xffffffffu, active && (st >> 62) == 0ULL));
                unsigned pm = __ballot_sync(0xffffffffu, active && (st >> 62) == 2ULL);
                unsigned long long val = active ? (st & VAL_MASK) : 0ULL;
                if (pm) {
                    int hp = 31 - __clz(pm);
                    if (lane < hp) val = 0ULL;
                    #pragma unroll
                    for (int o = 16; o > 0; o >>= 1) val += __shfl_down_sync(0xffffffffu, val, o);
                    exc += val;             // lane 0 holds total
                    break;
                } else {
                    #pragma unroll
                    for (int o = 16; o > 0; o >>= 1) val += __shfl_down_sync(0xffffffffu, val, o);
                    exc += val;
                    end = start;
                }
            }
            if (lane == 0) {
                unsigned long long incl = exc + agg;
                vstore(&g_state[bid], FLAG_PRE | incl);
                s_exc = exc;
                if (bid == NB1 - 1) g_P = (int)(incl >> 32);
            }
        }
    }
    __syncthreads();

    // downsweep: sparse writes at occupied pids
    unsigned long long e = s_exc + s_warp[wid] + (inc - run);
    #pragma unroll
    for (int k = 0; k < 8; k++) {
        unsigned ww = w[k];
        if (ww) {
            unsigned long long ee = e + pre[k];
            int pid0 = (int)((base + k) * 2);
            unsigned lo = ww & 0xffffu, hi = ww >> 16;
            if (lo) {
                g_vbase[pid0] = (unsigned)(ee & 0xffffffffu);
                g_pidlist[ee >> 32] = pid0;
                ee += (1ULL << 32) + (unsigned)__popc(lo);
            }
            if (hi) {
                g_vbase[pid0 + 1] = (unsigned)(ee & 0xffffffffu);
                g_pidlist[ee >> 32] = pid0 + 1;
            }
        }
    }
}

// -------- per-voxel linked lists + BN fold (block 0) --------
__global__ void k_link(const float* __restrict__ pts, const int* __restrict__ pmc,
                       const float* __restrict__ W,
                       const float* __restrict__ gamma,
                       const float* __restrict__ beta) {
    if (blockIdx.x == 0 && threadIdx.x < 64) {
        int c = threadIdx.x;
        double wc[8];
        #pragma unroll
        for (int k = 0; k < 8; k++) wc[k] = (double)W[k * 64 + c];
        const double invn = 1.0 / (double)N_PTS;
        double mu = 0.0;
        #pragma unroll
        for (int k = 0; k < 8; k++) mu += g_s[k] * invn * wc[k];
        double e2 = 0.0;
        #pragma unroll
        for (int k = 0; k < 8; k++) {
            for (int l = 0; l < k; l++) e2 += 2.0 * g_m[k * (k + 1) / 2 + l] * invn * wc[k] * wc[l];
            e2 += g_m[k * (k + 1) / 2 + k] * invn * wc[k] * wc[k];
        }
        double var = e2 - mu * mu;
        double scale = (double)gamma[c] / sqrt(var + 1e-3);
        #pragma unroll
        for (int k = 0; k < 8; k++) g_W2[k * 64 + c] = (float)(wc[k] * scale);
        g_shift[c] = (float)((double)beta[c] - mu * scale);
    }
    int i = blockIdx.x * blockDim.x + threadIdx.x;   // grid covers N_PTS exactly
    int pid = pmc[i];
    int zi = (int)__ldg(&pts[(size_t)i * 9 + 6]);
    unsigned w = g_zmask32[pid >> 1];
    unsigned zm = (w >> ((pid & 1) * 16)) & 0xffffu;
    int slot = (int)g_vbase[pid] + __popc(zm & ((1u << zi) - 1u));
    g_next[i] = atomicExch(&g_head[slot], i);
}

// ------ output: traverse pillar's voxel chains, inline matmul+BN+ReLU --------
__global__ void k_out(float* __restrict__ out,
                      const float* __restrict__ sparse,
                      const float* __restrict__ pts) {
    __shared__ float sW2[512];
    __shared__ float sSh[64];
    int t = threadIdx.x;
    for (int j = t; j < 512; j += 256) sW2[j] = g_W2[j];
    if (t < 64) sSh[t] = g_shift[t];
    __syncthreads();
    int g = t >> 4, lane = t & 15;
    int r = blockIdx.x * 16 + g;
    float4 sv = ((const float4*)sparse)[(size_t)r * 16 + lane];
    float4 res = sv;
    if (r < g_P) {
        int pid = g_pidlist[r];
        unsigned w = g_zmask32[pid >> 1];
        unsigned zm = (w >> ((pid & 1) * 16)) & 0xffffu;
        int nv = __popc(zm);
        if (nv >= 2) {                      // occupied: >=2 voxels in pillar
            int base = (int)g_vbase[pid];
            int c0 = lane * 4;
            float4 mx = make_float4(-3.4e38f, -3.4e38f, -3.4e38f, -3.4e38f);
            for (int j = 0; j < nv; j++) {
                int idx = g_head[base + j];
                float a0 = 0.f, a1 = 0.f, a2 = 0.f, a3 = 0.f;
                int cnt = 0;
                while (idx >= 0) {
                    const float* p = pts + (size_t)idx * 9;
                    int nxt = g_next[idx];
                    float x[8];
                    #pragma unroll
                    for (int k = 0; k < 8; k++) x[k] = __ldg(&p[1 + k]);
                    float h0 = sSh[c0], h1 = sSh[c0 + 1], h2 = sSh[c0 + 2], h3 = sSh[c0 + 3];
                    #pragma unroll
                    for (int k = 0; k < 8; k++) {
                        h0 = fmaf(x[k], sW2[k * 64 + c0],     h0);
                        h1 = fmaf(x[k], sW2[k * 64 + c0 + 1], h1);
                        h2 = fmaf(x[k], sW2[k * 64 + c0 + 2], h2);
                        h3 = fmaf(x[k], sW2[k * 64 + c0 + 3], h3);
                    }
                    a0 += fmaxf(h0, 0.f); a1 += fmaxf(h1, 0.f);
                    a2 += fmaxf(h2, 0.f); a3 += fmaxf(h3, 0.f);
                    cnt++;
                    idx = nxt;
                }
                float ic = 1.0f / (float)cnt;
                mx.x = fmaxf(mx.x, a0 * ic);
                mx.y = fmaxf(mx.y, a1 * ic);
                mx.z = fmaxf(mx.z, a2 * ic);
                mx.w = fmaxf(mx.w, a3 * ic);
            }
            float4 cand = make_float4(sv.x + mx.x, sv.y + mx.y, sv.z + mx.z, sv.w + mx.w);
            if (nv < 16) {
                cand.x = fmaxf(cand.x, 0.f); cand.y = fmaxf(cand.y, 0.f);
                cand.z = fmaxf(cand.z, 0.f); cand.w = fmaxf(cand.w, 0.f);
            }
            res = make_float4(sv.x + cand.x, sv.y + cand.y, sv.z + cand.z, sv.w + cand.w);
        }
    }
    ((float4*)out)[(size_t)r * 16 + lane] = res;
}

// ---------------- launch ----------------
extern "C" void kernel_launch(void* const* d_in, const int* in_sizes, int n_in,
                              void* d_out, int out_size) {
    const float* pts    = (const float*)d_in[0];  // [N,9]
    const float* sparse = (const float*)d_in[1];  // [N,64]
    const float* W      = (const float*)d_in[2];  // [8,64]
    const float* gamma  = (const float*)d_in[3];  // [64]
    const float* beta   = (const float*)d_in[4];  // [64]
    const int*   pmc    = (const int*)d_in[5];    // [N]
    float* out = (float*)d_out;

    kzero  <<<1024, 256>>>();
    k_stats<<<296, 256>>>(pts, pmc);
    k_scan <<<NB1, SCAN_BLK>>>();
    k_link <<<N_PTS / 256, 256>>>(pts, pmc, W, gamma, beta);
    k_out  <<<N_PTS / 16, 256>>>(out, sparse, pts);
}